// round 4
// baseline (speedup 1.0000x reference)
#include <cuda_runtime.h>
#include <cuda_fp16.h>

#define BB 32
#define TT 1000
#define EE 512
#define DD 1024
#define AA 512
#define CC 10
#define FF 100
#define KW 201
#define ODIM_ 5000
#define LL 100
#define OLEN 101
#define SOS_ 4998
#define NROW 4096
#define KCAT 2560
#define MOUT 3232
#define MOUT_PAD 3328
#define NBLK 148

__device__ __half g_preh[BB * TT * AA];
__device__ float g_wcat[NROW * KCAT];
__device__ float g_bcat[NROW];
__device__ float g_ey[OLEN][BB][DD];
__device__ float g_aw[BB * TT];
__device__ float g_e[BB * TT];
__device__ float g_conv[BB * CC * TT];
__device__ float g_decp[4][BB * AA];
__device__ float g_ctx[BB * EE];
__device__ float g_z[2][BB * DD];
__device__ float g_c[BB * DD];
__device__ float g_zall[MOUT_PAD * DD];
__device__ unsigned g_cnt;
__device__ volatile unsigned g_gen;

__device__ __forceinline__ float tanh_fast(float x) {
    float y;
    asm("tanh.approx.f32 %0, %1;" : "=f"(y) : "f"(x));
    return y;
}

__device__ __forceinline__ void gsync() {
    __syncthreads();
    if (threadIdx.x == 0) {
        unsigned gen = g_gen;
        __threadfence();
        if (atomicAdd(&g_cnt, 1u) == NBLK - 1) {
            g_cnt = 0;
            __threadfence();
            g_gen = gen + 1;
        } else {
            while (g_gen == gen) { }
        }
    }
    __syncthreads();
}

__global__ void k_init() {
    int i = blockIdx.x * blockDim.x + threadIdx.x;
    if (i < BB * DD) { g_z[0][i] = 0.f; g_c[i] = 0.f; }
    if (i < BB * TT) g_aw[i] = 1.0f / TT;
}

__global__ void k_ey(const int* __restrict__ ys, const float* __restrict__ embed) {
    int i = blockIdx.x * blockDim.x + threadIdx.x;
    int d = i & (DD - 1);
    int r = i >> 10;
    int b = r & 31;
    int s = r >> 5;
    int tok = (s == 0) ? SOS_ : ys[b * LL + s - 1];
    g_ey[s][b][d] = embed[(size_t)tok * DD + d];
}

__global__ void k_wcat(const float* __restrict__ w_ih, const float* __restrict__ w_hh,
                       const float* __restrict__ b_ih, const float* __restrict__ b_hh) {
    int i = blockIdx.x * blockDim.x + threadIdx.x;
    if (i < NROW * KCAT) {
        int r = i / KCAT, k = i - r * KCAT;
        int n = (r & 3) * DD + (r >> 2);
        g_wcat[i] = (k < DD + EE) ? w_ih[n * (DD + EE) + k] : w_hh[n * DD + (k - (DD + EE))];
    }
    if (i < NROW) {
        int n = (i & 3) * DD + (i >> 2);
        g_bcat[i] = b_ih[n] + b_hh[n];
    }
}

// C = A[MxK]*B[NxK]^T + bias. MODE 0: -> g_preh (fp16). MODE 1: out scatter.
template <int MODE>
__global__ __launch_bounds__(256) void k_sgemm(const float* __restrict__ Aarg,
                                               const float* __restrict__ Bm,
                                               const float* __restrict__ bias,
                                               float* __restrict__ Cout,
                                               int N, int K) {
    __shared__ float As[16][132];
    __shared__ float Bs[16][132];
    const float* A = (MODE == 1) ? g_zall : Aarg;
    int tid = threadIdx.x;
    int m0 = blockIdx.y * 128, n0 = blockIdx.x * 128;
    float acc[8][8];
#pragma unroll
    for (int i = 0; i < 8; i++)
#pragma unroll
        for (int j = 0; j < 8; j++) acc[i][j] = 0.f;
    int tm0 = (tid >> 4) << 3, tn0 = (tid & 15) << 3;
    for (int k0 = 0; k0 < K; k0 += 16) {
#pragma unroll
        for (int i = 0; i < 2; i++) {
            int lin = tid + (i << 8);
            int row = lin >> 2, kq = (lin & 3) << 2;
            float4 va = *(const float4*)(A + (size_t)(m0 + row) * K + k0 + kq);
            As[kq + 0][row] = va.x; As[kq + 1][row] = va.y;
            As[kq + 2][row] = va.z; As[kq + 3][row] = va.w;
            int nr = n0 + row;
            float4 vb = make_float4(0.f, 0.f, 0.f, 0.f);
            if (MODE == 0 || nr < N) vb = *(const float4*)(Bm + (size_t)nr * K + k0 + kq);
            Bs[kq + 0][row] = vb.x; Bs[kq + 1][row] = vb.y;
            Bs[kq + 2][row] = vb.z; Bs[kq + 3][row] = vb.w;
        }
        __syncthreads();
#pragma unroll
        for (int kk = 0; kk < 16; kk++) {
            float a[8], b[8];
            *(float4*)&a[0] = *(const float4*)&As[kk][tm0];
            *(float4*)&a[4] = *(const float4*)&As[kk][tm0 + 4];
            *(float4*)&b[0] = *(const float4*)&Bs[kk][tn0];
            *(float4*)&b[4] = *(const float4*)&Bs[kk][tn0 + 4];
#pragma unroll
            for (int i = 0; i < 8; i++)
#pragma unroll
                for (int j = 0; j < 8; j++)
                    acc[i][j] = fmaf(a[i], b[j], acc[i][j]);
        }
        __syncthreads();
    }
#pragma unroll
    for (int i = 0; i < 8; i++) {
        int m_ = m0 + tm0 + i;
#pragma unroll
        for (int j = 0; j < 8; j++) {
            int n_ = n0 + tn0 + j;
            if (MODE == 1 && n_ >= N) continue;
            float v = acc[i][j] + bias[n_];
            if (MODE == 1) {
                if (m_ < MOUT) {
                    int b_ = m_ & 31, o_ = m_ >> 5;
                    Cout[(size_t)(b_ * OLEN + o_) * ODIM_ + n_] = v;
                }
            } else {
                g_preh[(size_t)m_ * N + n_] = __float2half(v);
            }
        }
    }
}

// ---------------- persistent step-loop kernel ----------------
__device__ __forceinline__ void conv_unit(int u, const float* __restrict__ w_conv,
                                          float* smem) {
    int tid = threadIdx.x;
    int b = u / CC, c = u - b * CC;
    float* aw_s = smem;          // 1200
    float* wk = smem + 1200;     // 201
    __syncthreads();
    for (int i = tid; i < TT + 2 * FF; i += 256)
        aw_s[i] = (i >= FF && i < FF + TT) ? g_aw[b * TT + i - FF] : 0.f;
    for (int i = tid; i < KW; i += 256) wk[i] = w_conv[c * KW + i];
    __syncthreads();
    for (int t = tid; t < TT; t += 256) {
        float s = 0.f;
#pragma unroll 4
        for (int k = 0; k < KW; k++) s = fmaf(wk[k], aw_s[t + k], s);
        g_conv[(b * CC + c) * TT + t] = s;
    }
}

__device__ __forceinline__ void dec_unit(int v, int par, const float* __restrict__ w_dec,
                                         float* smem) {
    int tid = threadIdx.x;
    float* ws2 = smem;           // [32][68]
    float* zs = smem + 2176;     // [64][36]
    int ks = v & 3, at = v >> 2;
    int a0 = at * 32;
    int kbase = ks * 256;
    int al = tid >> 3, bq = (tid & 7) << 2;
    int bbz = tid >> 3, kk0 = tid & 7;
    const float* zsrc = g_z[par];
    float a0v = 0.f, a1v = 0.f, a2v = 0.f, a3v = 0.f;
    for (int kc = 0; kc < 4; kc++) {
        int k0 = kbase + kc * 64;
        __syncthreads();
#pragma unroll
        for (int i = 0; i < 2; i++) {
            int lin = tid + (i << 8);
            int row = lin >> 4, kq = (lin & 15) << 2;
            float4 w4 = *(const float4*)(w_dec + (size_t)(a0 + row) * DD + k0 + kq);
            ws2[row * 68 + kq + 0] = w4.x; ws2[row * 68 + kq + 1] = w4.y;
            ws2[row * 68 + kq + 2] = w4.z; ws2[row * 68 + kq + 3] = w4.w;
        }
#pragma unroll
        for (int j = 0; j < 8; j++) {
            int kk = kk0 + (j << 3);
            zs[kk * 36 + bbz] = zsrc[bbz * DD + k0 + kk];
        }
        __syncthreads();
#pragma unroll
        for (int kk = 0; kk < 64; kk++) {
            float w = ws2[al * 68 + kk];
            float4 x = *(const float4*)&zs[kk * 36 + bq];
            a0v = fmaf(w, x.x, a0v); a1v = fmaf(w, x.y, a1v);
            a2v = fmaf(w, x.z, a2v); a3v = fmaf(w, x.w, a3v);
        }
    }
    g_decp[ks][(bq + 0) * AA + a0 + al] = a0v;
    g_decp[ks][(bq + 1) * AA + a0 + al] = a1v;
    g_decp[ks][(bq + 2) * AA + a0 + al] = a2v;
    g_decp[ks][(bq + 3) * AA + a0 + al] = a3v;
}

__device__ __forceinline__ void e_unit(int u, const float* __restrict__ w_att,
                                       const float* __restrict__ w_gvec, float* smem) {
    int tid = threadIdx.x;
    int b = u / 40, t0 = (u - b * 40) * 25;
    float* conv_s = smem;        // [25][10]
    float* part_s = smem + 256;  // [25][8]
    __syncthreads();
    for (int i = tid; i < 250; i += 256) {
        int c = i / 25, tl = i - c * 25;
        conv_s[tl * 10 + c] = g_conv[(b * CC + c) * TT + t0 + tl];
    }
    int a0 = tid * 2;
    float wr[2][10], gg[2], dc[2];
#pragma unroll
    for (int j = 0; j < 2; j++) {
#pragma unroll
        for (int c = 0; c < 10; c++) wr[j][c] = w_att[(a0 + j) * CC + c];
        gg[j] = w_gvec[a0 + j];
        int ai = b * AA + a0 + j;
        dc[j] = g_decp[0][ai] + g_decp[1][ai] + g_decp[2][ai] + g_decp[3][ai];
    }
    __syncthreads();
    int lane = tid & 31, warp = tid >> 5;
    const __half* prep = g_preh + ((size_t)b * TT + t0) * AA + a0;
    for (int tl = 0; tl < 25; tl++) {
        __half2 h2 = *(const __half2*)(prep + (size_t)tl * AA);
        float2 f = __half22float2(h2);
        float pa[2] = {f.x, f.y};
        float acc = 0.f;
#pragma unroll
        for (int j = 0; j < 2; j++) {
            float x = pa[j] + dc[j];
#pragma unroll
            for (int c = 0; c < 10; c++) x = fmaf(conv_s[tl * 10 + c], wr[j][c], x);
            acc = fmaf(gg[j], tanh_fast(x), acc);
        }
#pragma unroll
        for (int s = 16; s; s >>= 1) acc += __shfl_xor_sync(0xffffffffu, acc, s);
        if (lane == 0) part_s[tl * 8 + warp] = acc;
    }
    __syncthreads();
    if (tid < 25) {
        float s = 0.f;
#pragma unroll
        for (int w = 0; w < 8; w++) s += part_s[tid * 8 + w];
        g_e[b * TT + t0 + tid] = s;
    }
}

__device__ __forceinline__ void ctx_unit(int u, const float* __restrict__ hpad,
                                         float* smem) {
    int tid = threadIdx.x;
    int b = u >> 2, ec = u & 3;
    float* wsm = smem;           // [1000]
    float* red = smem + 1024;    // [256]
    __syncthreads();
    const float* ep = g_e + b * TT;
    float m = -1e30f;
    for (int t = tid; t < TT; t += 256) m = fmaxf(m, ep[t]);
    red[tid] = m; __syncthreads();
    for (int s = 128; s; s >>= 1) {
        if (tid < s) red[tid] = fmaxf(red[tid], red[tid + s]);
        __syncthreads();
    }
    float mx = red[0]; __syncthreads();
    float sm = 0.f;
    for (int t = tid; t < TT; t += 256) sm += __expf(2.f * (ep[t] - mx));
    red[tid] = sm; __syncthreads();
    for (int s = 128; s; s >>= 1) {
        if (tid < s) red[tid] += red[tid + s];
        __syncthreads();
    }
    float inv = 1.f / red[0];
    __syncthreads();
    for (int t = tid; t < TT; t += 256) {
        float w = __expf(2.f * (ep[t] - mx)) * inv;
        wsm[t] = w;
        if (ec == 0) g_aw[b * TT + t] = w;
    }
    __syncthreads();
    int el = tid & 127, h = tid >> 7;
    int e0 = ec * 128;
    const float* hp = hpad + ((size_t)b * TT + h * 500) * EE + e0 + el;
    const float* wp = wsm + h * 500;
    float a0 = 0.f, a1 = 0.f, a2 = 0.f, a3 = 0.f;
#pragma unroll 1
    for (int i = 0; i < 500; i += 4) {
        a0 = fmaf(wp[i + 0], hp[(size_t)(i + 0) * EE], a0);
        a1 = fmaf(wp[i + 1], hp[(size_t)(i + 1) * EE], a1);
        a2 = fmaf(wp[i + 2], hp[(size_t)(i + 2) * EE], a2);
        a3 = fmaf(wp[i + 3], hp[(size_t)(i + 3) * EE], a3);
    }
    red[tid] = (a0 + a1) + (a2 + a3);
    __syncthreads();
    if (tid < 128) g_ctx[b * EE + e0 + tid] = red[tid] + red[tid + 128];
}

__device__ __forceinline__ void lstm_unit(int u, int step, int par, float* smem) {
    int tid = threadIdx.x;
    float* ws = smem;              // [32][68]
    float* xs = smem + 2176;       // [64][36]
    float* gates = smem + 4480;    // [32][33]
    int r0 = u * 32;
    int rl = tid >> 3, b0 = (tid & 7) << 2;
    int bbx = tid >> 3, kk0x = tid & 7;
    const float* zsrc = g_z[par];
    const float* eyp = &g_ey[step][0][0];
    float acc0 = 0.f, acc1 = 0.f, acc2 = 0.f, acc3 = 0.f;
    for (int k0 = 0; k0 < KCAT; k0 += 64) {
        __syncthreads();
#pragma unroll
        for (int i = 0; i < 2; i++) {
            int lin = tid + (i << 8);
            int row = lin >> 4, kq = (lin & 15) << 2;
            float4 w4 = *(const float4*)(g_wcat + (size_t)(r0 + row) * KCAT + k0 + kq);
            ws[row * 68 + kq + 0] = w4.x; ws[row * 68 + kq + 1] = w4.y;
            ws[row * 68 + kq + 2] = w4.z; ws[row * 68 + kq + 3] = w4.w;
        }
#pragma unroll
        for (int j = 0; j < 8; j++) {
            int kk = kk0x + (j << 3);
            int k = k0 + kk;
            float v;
            if (k < DD) v = eyp[bbx * DD + k];
            else if (k < DD + EE) v = g_ctx[bbx * EE + (k - DD)];
            else v = zsrc[bbx * DD + (k - DD - EE)];
            xs[kk * 36 + bbx] = v;
        }
        __syncthreads();
#pragma unroll
        for (int kk = 0; kk < 64; kk++) {
            float w = ws[rl * 68 + kk];
            float4 x = *(const float4*)&xs[kk * 36 + b0];
            acc0 = fmaf(w, x.x, acc0); acc1 = fmaf(w, x.y, acc1);
            acc2 = fmaf(w, x.z, acc2); acc3 = fmaf(w, x.w, acc3);
        }
    }
    __syncthreads();
    float bias = g_bcat[r0 + rl];
    gates[rl * 33 + b0 + 0] = acc0 + bias;
    gates[rl * 33 + b0 + 1] = acc1 + bias;
    gates[rl * 33 + b0 + 2] = acc2 + bias;
    gates[rl * 33 + b0 + 3] = acc3 + bias;
    __syncthreads();
    int dl = tid >> 5, b = tid & 31;
    int d = (r0 >> 2) + dl;
    float iv = gates[(dl * 4 + 0) * 33 + b];
    float fv = gates[(dl * 4 + 1) * 33 + b];
    float gv = gates[(dl * 4 + 2) * 33 + b];
    float ov = gates[(dl * 4 + 3) * 33 + b];
    float si = 1.f / (1.f + expf(-iv));
    float sf = 1.f / (1.f + expf(-fv));
    float so = 1.f / (1.f + expf(-ov));
    float cn = sf * g_c[b * DD + d] + si * tanhf(gv);
    float zn = so * tanhf(cn);
    g_c[b * DD + d] = cn;
    g_z[par ^ 1][b * DD + d] = zn;
    g_zall[(size_t)(step * BB + b) * DD + d] = zn;
}

__global__ __launch_bounds__(256) void k_steps(const float* __restrict__ hpad,
                                               const float* __restrict__ w_dec,
                                               const float* __restrict__ w_conv,
                                               const float* __restrict__ w_att,
                                               const float* __restrict__ w_gvec) {
    __shared__ float smem[6144];
    int blk = blockIdx.x;
    for (int step = 0; step < OLEN; step++) {
        int par = step & 1;
        // S1: conv (320 units) + dec (64 units)
        for (int u = blk; u < 384; u += NBLK) {
            if (u < 320) conv_unit(u, w_conv, smem);
            else dec_unit(u - 320, par, w_dec, smem);
        }
        gsync();
        // S2: e (1280 units: 32 b x 40 t-chunks of 25)
        for (int u = blk; u < 1280; u += NBLK) e_unit(u, w_att, w_gvec, smem);
        gsync();
        // S3: softmax + ctx + aw (128 units: 32 b x 4 e-chunks)
        for (int u = blk; u < 128; u += NBLK) ctx_unit(u, hpad, smem);
        gsync();
        // S4: LSTM (128 units: r-tiles of 32)
        for (int u = blk; u < 128; u += NBLK) lstm_unit(u, step, par, smem);
        gsync();
    }
}

extern "C" void kernel_launch(void* const* d_in, const int* in_sizes, int n_in,
                              void* d_out, int out_size) {
    const float* hpad   = (const float*)d_in[0];
    const int*   ys     = (const int*)d_in[1];
    const float* w_enc  = (const float*)d_in[2];
    const float* b_enc  = (const float*)d_in[3];
    const float* w_dec  = (const float*)d_in[4];
    const float* w_att  = (const float*)d_in[5];
    const float* w_conv = (const float*)d_in[6];
    const float* w_gvec = (const float*)d_in[7];
    const float* embed  = (const float*)d_in[9];
    const float* w_ih   = (const float*)d_in[10];
    const float* w_hh   = (const float*)d_in[11];
    const float* b_ih   = (const float*)d_in[12];
    const float* b_hh   = (const float*)d_in[13];
    const float* w_out  = (const float*)d_in[14];
    const float* b_out  = (const float*)d_in[15];
    float* out = (float*)d_out;

    k_init<<<128, 256>>>();
    k_ey<<<(OLEN * BB * DD) / 256, 256>>>(ys, embed);
    k_wcat<<<(NROW * KCAT + 255) / 256, 256>>>(w_ih, w_hh, b_ih, b_hh);
    k_sgemm<0><<<dim3(4, 250), 256>>>(hpad, w_enc, b_enc, nullptr, 512, 512);
    k_steps<<<NBLK, 256>>>(hpad, w_dec, w_conv, w_att, w_gvec);
    k_sgemm<1><<<dim3(40, 26), 256>>>(nullptr, w_out, b_out, out, ODIM_, DD);
}

// round 5
// speedup vs baseline: 2.1982x; 2.1982x over previous
#include <cuda_runtime.h>
#include <cuda_fp16.h>

#define BB 32
#define TT 1000
#define EE 512
#define DD 1024
#define AA 512
#define CC 10
#define FF 100
#define KW 201
#define ODIM_ 5000
#define LL 100
#define OLEN 101
#define SOS_ 4998
#define NROW 4096
#define KCAT2 1536
#define MOUT 3232
#define MOUT_PAD 3328

__device__ __half g_preh[BB * TT * AA];          // fp16 pre, 32.8 MB
__device__ __half g_hpadh[BB * TT * EE];         // fp16 hpad, 32.8 MB
__device__ float g_wcat2[NROW * KCAT2];          // [ctx|z] weights, 25.2 MB
__device__ float g_gey[MOUT_PAD * NROW];         // precomputed W_ih[:, :1024]@ey + bias, 54.5 MB
__device__ float g_aw[BB * TT];
__device__ float g_e[BB * TT];
__device__ float g_conv[BB * CC * TT];
__device__ float g_dec[BB * AA];
__device__ float g_ctx[BB * EE];
__device__ float g_z[2][BB * DD];
__device__ float g_c[BB * DD];
__device__ float g_zall[MOUT_PAD * DD];

__device__ __forceinline__ float tanh_fast(float x) {
    float y;
    asm("tanh.approx.f32 %0, %1;" : "=f"(y) : "f"(x));
    return y;
}

// ---------- pre-loop kernel 1: init + weight pack + hpad->fp16 ----------
__global__ void k_prep(const float* __restrict__ w_ih, const float* __restrict__ w_hh,
                       const float* __restrict__ hpad) {
    const size_t TOT = 22740224;
    for (size_t i = (size_t)blockIdx.x * 256 + threadIdx.x; i < TOT; i += 2097152) {
        if (i < 32768) {
            g_z[0][i] = 0.f; g_c[i] = 0.f;
        } else if (i < 64768) {
            g_aw[i - 32768] = 1.0f / TT;
        } else if (i < 6356224) {
            int j = (int)(i - 64768);
            int r = j / KCAT2, k = j - r * KCAT2;
            int n = (r & 3) * DD + (r >> 2);
            g_wcat2[j] = (k < EE) ? w_ih[(size_t)n * (DD + EE) + DD + k]
                                  : w_hh[(size_t)n * DD + (k - EE)];
        } else {
            size_t j = i - 6356224;
            g_hpadh[j] = __float2half(hpad[j]);
        }
    }
}

// ---------- pre-loop kernel 2: fused one-time GEMMs ----------
// blocks [0,832): gey = ey @ W_ih[:, :1024]^T + bias  (M=3328, N=4096, K=1024)
// blocks [832,1832): pre = hpad @ w_enc^T + b_enc -> fp16 (M=32000, N=512, K=512)
__global__ __launch_bounds__(256) void k_gemms(const float* __restrict__ hpad,
                                               const float* __restrict__ w_enc,
                                               const float* __restrict__ b_enc,
                                               const float* __restrict__ w_ih,
                                               const float* __restrict__ b_ih,
                                               const float* __restrict__ b_hh,
                                               const int* __restrict__ ys,
                                               const float* __restrict__ embed) {
    __shared__ float As[16][132];
    __shared__ float Bs[16][132];
    __shared__ int tok_s[128];
    int tid = threadIdx.x;
    bool is_pre = blockIdx.x >= 832;
    int m0, n0, K;
    if (is_pre) {
        int idx = blockIdx.x - 832;
        m0 = (idx >> 2) * 128; n0 = (idx & 3) * 128; K = 512;
    } else {
        m0 = ((int)blockIdx.x >> 5) * 128; n0 = ((int)blockIdx.x & 31) * 128; K = 1024;
        if (tid < 128) {
            int m = m0 + tid;
            int s = m >> 5, b = m & 31;
            tok_s[tid] = (s == 0 || s > 100) ? SOS_ : ys[b * LL + s - 1];
        }
        __syncthreads();
    }
    float acc[8][8];
#pragma unroll
    for (int i = 0; i < 8; i++)
#pragma unroll
        for (int j = 0; j < 8; j++) acc[i][j] = 0.f;
    int tm0 = (tid >> 4) << 3, tn0 = (tid & 15) << 3;
    for (int k0 = 0; k0 < K; k0 += 16) {
#pragma unroll
        for (int i = 0; i < 2; i++) {
            int lin = tid + (i << 8);
            int row = lin >> 2, kq = (lin & 3) << 2;
            float4 va, vb;
            if (is_pre) {
                va = *(const float4*)(hpad + (size_t)(m0 + row) * 512 + k0 + kq);
                vb = *(const float4*)(w_enc + (size_t)(n0 + row) * 512 + k0 + kq);
            } else {
                va = *(const float4*)(embed + (size_t)tok_s[row] * DD + k0 + kq);
                int r = n0 + row;
                int orig = (r & 3) * DD + (r >> 2);
                vb = *(const float4*)(w_ih + (size_t)orig * (DD + EE) + k0 + kq);
            }
            As[kq + 0][row] = va.x; As[kq + 1][row] = va.y;
            As[kq + 2][row] = va.z; As[kq + 3][row] = va.w;
            Bs[kq + 0][row] = vb.x; Bs[kq + 1][row] = vb.y;
            Bs[kq + 2][row] = vb.z; Bs[kq + 3][row] = vb.w;
        }
        __syncthreads();
#pragma unroll
        for (int kk = 0; kk < 16; kk++) {
            float a[8], b[8];
            *(float4*)&a[0] = *(const float4*)&As[kk][tm0];
            *(float4*)&a[4] = *(const float4*)&As[kk][tm0 + 4];
            *(float4*)&b[0] = *(const float4*)&Bs[kk][tn0];
            *(float4*)&b[4] = *(const float4*)&Bs[kk][tn0 + 4];
#pragma unroll
            for (int i = 0; i < 8; i++)
#pragma unroll
                for (int j = 0; j < 8; j++)
                    acc[i][j] = fmaf(a[i], b[j], acc[i][j]);
        }
        __syncthreads();
    }
#pragma unroll
    for (int i = 0; i < 8; i++) {
        int m_ = m0 + tm0 + i;
#pragma unroll
        for (int j = 0; j < 8; j++) {
            int n_ = n0 + tn0 + j;
            if (is_pre) {
                g_preh[(size_t)m_ * 512 + n_] = __float2half(acc[i][j] + b_enc[n_]);
            } else {
                int orig = (n_ & 3) * DD + (n_ >> 2);
                g_gey[(size_t)m_ * NROW + n_] = acc[i][j] + b_ih[orig] + b_hh[orig];
            }
        }
    }
}

// ---------- per-step: conv(aw) [blocks 0..319] + dec = z@w_dec^T [blocks 320..831] ----------
__global__ __launch_bounds__(256) void k_small(const float* __restrict__ w_dec,
                                               const float* __restrict__ w_conv, int step) {
    __shared__ float sm[1408];
    int blk = blockIdx.x, tid = threadIdx.x;
    if (blk < BB * CC) {
        int b = blk / CC, c = blk - b * CC;
        float* aw_s = sm;
        float* wk = sm + 1200;
        for (int i = tid; i < TT + 2 * FF; i += 256)
            aw_s[i] = (i >= FF && i < FF + TT) ? g_aw[b * TT + i - FF] : 0.f;
        for (int i = tid; i < KW; i += 256) wk[i] = w_conv[c * KW + i];
        __syncthreads();
        for (int t = tid; t < TT; t += 256) {
            float s = 0.f;
#pragma unroll 4
            for (int k = 0; k < KW; k++) s = fmaf(wk[k], aw_s[t + k], s);
            g_conv[(b * CC + c) * TT + t] = s;
        }
    } else {
        int warp = tid >> 5, lane = tid & 31;
        int o0 = (blk - BB * CC) * 32 + warp * 4;
        int b = o0 >> 9, a0 = o0 & (AA - 1);
        const float* zp = g_z[step & 1] + b * DD;
        float s0 = 0.f, s1 = 0.f, s2 = 0.f, s3 = 0.f;
        for (int k = lane * 4; k < DD; k += 128) {
            float4 zv = *(const float4*)(zp + k);
            float4 w0 = *(const float4*)(w_dec + (size_t)(a0 + 0) * DD + k);
            float4 w1 = *(const float4*)(w_dec + (size_t)(a0 + 1) * DD + k);
            float4 w2 = *(const float4*)(w_dec + (size_t)(a0 + 2) * DD + k);
            float4 w3 = *(const float4*)(w_dec + (size_t)(a0 + 3) * DD + k);
            s0 += zv.x * w0.x + zv.y * w0.y + zv.z * w0.z + zv.w * w0.w;
            s1 += zv.x * w1.x + zv.y * w1.y + zv.z * w1.z + zv.w * w1.w;
            s2 += zv.x * w2.x + zv.y * w2.y + zv.z * w2.z + zv.w * w2.w;
            s3 += zv.x * w3.x + zv.y * w3.y + zv.z * w3.z + zv.w * w3.w;
        }
#pragma unroll
        for (int s = 16; s; s >>= 1) {
            s0 += __shfl_xor_sync(0xffffffffu, s0, s);
            s1 += __shfl_xor_sync(0xffffffffu, s1, s);
            s2 += __shfl_xor_sync(0xffffffffu, s2, s);
            s3 += __shfl_xor_sync(0xffffffffu, s3, s);
        }
        if (lane == 0) {
            g_dec[b * AA + a0 + 0] = s0;
            g_dec[b * AA + a0 + 1] = s1;
            g_dec[b * AA + a0 + 2] = s2;
            g_dec[b * AA + a0 + 3] = s3;
        }
    }
}

// ---------- per-step: e[b,t] = sum_a g[a]*tanh(pre+dec+conv@w_att^T) ----------
__global__ __launch_bounds__(128) void k_e(const float* __restrict__ w_att,
                                           const float* __restrict__ w_gvec) {
    int b = blockIdx.y, t0 = blockIdx.x * 40;
    int tid = threadIdx.x;
    __shared__ float conv_s[40][10];
    __shared__ float part_s[40][4];
    for (int i = tid; i < 400; i += 128) {
        int c = i / 40, tl = i - c * 40;
        conv_s[tl][c] = g_conv[(b * CC + c) * TT + t0 + tl];
    }
    int a0 = tid * 4;
    float wr[4][10], gg[4], dc[4];
#pragma unroll
    for (int j = 0; j < 4; j++) {
#pragma unroll
        for (int c = 0; c < 10; c++) wr[j][c] = w_att[(a0 + j) * CC + c];
        gg[j] = w_gvec[a0 + j];
        dc[j] = g_dec[b * AA + a0 + j];
    }
    __syncthreads();
    int lane = tid & 31, warp = tid >> 5;
    const __half* prep = g_preh + ((size_t)b * TT + t0) * AA + a0;
    for (int tl = 0; tl < 40; tl++) {
        uint2 u = *(const uint2*)(prep + (size_t)tl * AA);
        __half2 h01 = *reinterpret_cast<__half2*>(&u.x);
        __half2 h23 = *reinterpret_cast<__half2*>(&u.y);
        float2 f01 = __half22float2(h01);
        float2 f23 = __half22float2(h23);
        float pa[4] = {f01.x, f01.y, f23.x, f23.y};
        float acc = 0.f;
#pragma unroll
        for (int j = 0; j < 4; j++) {
            float x = pa[j] + dc[j];
#pragma unroll
            for (int c = 0; c < 10; c++) x = fmaf(conv_s[tl][c], wr[j][c], x);
            acc = fmaf(gg[j], tanh_fast(x), acc);
        }
#pragma unroll
        for (int s = 16; s; s >>= 1) acc += __shfl_xor_sync(0xffffffffu, acc, s);
        if (lane == 0) part_s[tl][warp] = acc;
    }
    __syncthreads();
    if (tid < 40)
        g_e[b * TT + t0 + tid] =
            part_s[tid][0] + part_s[tid][1] + part_s[tid][2] + part_s[tid][3];
}

// ---------- per-step: softmax(2e) + ctx (full T per block) + aw ----------
__global__ __launch_bounds__(256) void k_ctx() {
    int b = blockIdx.y, ec = blockIdx.x;
    int tid = threadIdx.x;
    __shared__ float wsm[1000];
    __shared__ float red[256];
    const float* ep = g_e + b * TT;
    float m = -1e30f;
    for (int t = tid; t < TT; t += 256) m = fmaxf(m, ep[t]);
    red[tid] = m; __syncthreads();
    for (int s = 128; s; s >>= 1) {
        if (tid < s) red[tid] = fmaxf(red[tid], red[tid + s]);
        __syncthreads();
    }
    float mx = red[0]; __syncthreads();
    float sm = 0.f;
    for (int t = tid; t < TT; t += 256) sm += __expf(2.f * (ep[t] - mx));
    red[tid] = sm; __syncthreads();
    for (int s = 128; s; s >>= 1) {
        if (tid < s) red[tid] += red[tid + s];
        __syncthreads();
    }
    float inv = 1.f / red[0];
    __syncthreads();
    for (int t = tid; t < TT; t += 256) {
        float w = __expf(2.f * (ep[t] - mx)) * inv;
        wsm[t] = w;
        if (ec == 0) g_aw[b * TT + t] = w;
    }
    __syncthreads();
    int el = tid & 127, h = tid >> 7;
    int e0 = ec * 128;
    const __half* hp = g_hpadh + ((size_t)b * TT + h * 500) * EE + e0 + el;
    const float* wp = wsm + h * 500;
    float a0 = 0.f, a1 = 0.f, a2 = 0.f, a3 = 0.f;
#pragma unroll 1
    for (int i = 0; i < 500; i += 4) {
        a0 = fmaf(wp[i + 0], __half2float(hp[(size_t)(i + 0) * EE]), a0);
        a1 = fmaf(wp[i + 1], __half2float(hp[(size_t)(i + 1) * EE]), a1);
        a2 = fmaf(wp[i + 2], __half2float(hp[(size_t)(i + 2) * EE]), a2);
        a3 = fmaf(wp[i + 3], __half2float(hp[(size_t)(i + 3) * EE]), a3);
    }
    red[tid] = (a0 + a1) + (a2 + a3);
    __syncthreads();
    if (tid < 128) g_ctx[b * EE + e0 + tid] = red[tid] + red[tid + 128];
}

// ---------- per-step: LSTM gates (K=1536: ctx|z) + cell, acc init from g_gey ----------
__global__ __launch_bounds__(256) void k_lstm(int step) {
    __shared__ float ws[32][68];
    __shared__ float xs[64][36];
    __shared__ float gates_s[32][33];
    int tid = threadIdx.x;
    int r0 = blockIdx.x * 32;
    int zr = step & 1;
    int rl = tid >> 3, b0 = (tid & 7) << 2;
    int bb = tid >> 3, kk0 = tid & 7;
    float acc0 = g_gey[(size_t)(step * BB + b0 + 0) * NROW + r0 + rl];
    float acc1 = g_gey[(size_t)(step * BB + b0 + 1) * NROW + r0 + rl];
    float acc2 = g_gey[(size_t)(step * BB + b0 + 2) * NROW + r0 + rl];
    float acc3 = g_gey[(size_t)(step * BB + b0 + 3) * NROW + r0 + rl];
    const float* zsrc = g_z[zr];
    for (int k0 = 0; k0 < KCAT2; k0 += 64) {
#pragma unroll
        for (int i = 0; i < 2; i++) {
            int lin = tid + (i << 8);
            int row = lin >> 4, kq = (lin & 15) << 2;
            float4 w4 = *(const float4*)(g_wcat2 + (size_t)(r0 + row) * KCAT2 + k0 + kq);
            ws[row][kq + 0] = w4.x; ws[row][kq + 1] = w4.y;
            ws[row][kq + 2] = w4.z; ws[row][kq + 3] = w4.w;
        }
#pragma unroll
        for (int j = 0; j < 8; j++) {
            int kk = kk0 + (j << 3);
            int k = k0 + kk;
            float v;
            if (k < EE) v = g_ctx[bb * EE + k];
            else v = zsrc[bb * DD + (k - EE)];
            xs[kk][bb] = v;
        }
        __syncthreads();
#pragma unroll
        for (int kk = 0; kk < 64; kk++) {
            float w = ws[rl][kk];
            float4 x = *(const float4*)&xs[kk][b0];
            acc0 = fmaf(w, x.x, acc0); acc1 = fmaf(w, x.y, acc1);
            acc2 = fmaf(w, x.z, acc2); acc3 = fmaf(w, x.w, acc3);
        }
        __syncthreads();
    }
    gates_s[rl][b0 + 0] = acc0;
    gates_s[rl][b0 + 1] = acc1;
    gates_s[rl][b0 + 2] = acc2;
    gates_s[rl][b0 + 3] = acc3;
    __syncthreads();
    int dl = tid >> 5, b = tid & 31;
    int d = (r0 >> 2) + dl;
    float iv = gates_s[dl * 4 + 0][b];
    float fv = gates_s[dl * 4 + 1][b];
    float gv = gates_s[dl * 4 + 2][b];
    float ov = gates_s[dl * 4 + 3][b];
    float si = 1.f / (1.f + expf(-iv));
    float sf = 1.f / (1.f + expf(-fv));
    float so = 1.f / (1.f + expf(-ov));
    float cn = sf * g_c[b * DD + d] + si * tanhf(gv);
    float zn = so * tanhf(cn);
    g_c[b * DD + d] = cn;
    g_z[zr ^ 1][b * DD + d] = zn;
    g_zall[(size_t)(step * BB + b) * DD + d] = zn;
}

// ---------- final: out = z_all @ w_out^T + b_out, scatter to [B, OLEN, ODIM] ----------
__global__ __launch_bounds__(256) void k_out(const float* __restrict__ Bm,
                                             const float* __restrict__ bias,
                                             float* __restrict__ Cout) {
    __shared__ float As[16][132];
    __shared__ float Bs[16][132];
    int tid = threadIdx.x;
    int m0 = blockIdx.y * 128, n0 = blockIdx.x * 128;
    float acc[8][8];
#pragma unroll
    for (int i = 0; i < 8; i++)
#pragma unroll
        for (int j = 0; j < 8; j++) acc[i][j] = 0.f;
    int tm0 = (tid >> 4) << 3, tn0 = (tid & 15) << 3;
    for (int k0 = 0; k0 < DD; k0 += 16) {
#pragma unroll
        for (int i = 0; i < 2; i++) {
            int lin = tid + (i << 8);
            int row = lin >> 2, kq = (lin & 3) << 2;
            float4 va = *(const float4*)(g_zall + (size_t)(m0 + row) * DD + k0 + kq);
            As[kq + 0][row] = va.x; As[kq + 1][row] = va.y;
            As[kq + 2][row] = va.z; As[kq + 3][row] = va.w;
            int nr = n0 + row;
            float4 vb = make_float4(0.f, 0.f, 0.f, 0.f);
            if (nr < ODIM_) vb = *(const float4*)(Bm + (size_t)nr * DD + k0 + kq);
            Bs[kq + 0][row] = vb.x; Bs[kq + 1][row] = vb.y;
            Bs[kq + 2][row] = vb.z; Bs[kq + 3][row] = vb.w;
        }
        __syncthreads();
#pragma unroll
        for (int kk = 0; kk < 16; kk++) {
            float a[8], b[8];
            *(float4*)&a[0] = *(const float4*)&As[kk][tm0];
            *(float4*)&a[4] = *(const float4*)&As[kk][tm0 + 4];
            *(float4*)&b[0] = *(const float4*)&Bs[kk][tn0];
            *(float4*)&b[4] = *(const float4*)&Bs[kk][tn0 + 4];
#pragma unroll
            for (int i = 0; i < 8; i++)
#pragma unroll
                for (int j = 0; j < 8; j++)
                    acc[i][j] = fmaf(a[i], b[j], acc[i][j]);
        }
        __syncthreads();
    }
#pragma unroll
    for (int i = 0; i < 8; i++) {
        int m_ = m0 + tm0 + i;
        if (m_ >= MOUT) continue;
        int b_ = m_ & 31, o_ = m_ >> 5;
#pragma unroll
        for (int j = 0; j < 8; j++) {
            int n_ = n0 + tn0 + j;
            if (n_ >= ODIM_) continue;
            Cout[(size_t)(b_ * OLEN + o_) * ODIM_ + n_] = acc[i][j] + bias[n_];
        }
    }
}

extern "C" void kernel_launch(void* const* d_in, const int* in_sizes, int n_in,
                              void* d_out, int out_size) {
    const float* hpad   = (const float*)d_in[0];
    const int*   ys     = (const int*)d_in[1];
    const float* w_enc  = (const float*)d_in[2];
    const float* b_enc  = (const float*)d_in[3];
    const float* w_dec  = (const float*)d_in[4];
    const float* w_att  = (const float*)d_in[5];
    const float* w_conv = (const float*)d_in[6];
    const float* w_gvec = (const float*)d_in[7];
    const float* embed  = (const float*)d_in[9];
    const float* w_ih   = (const float*)d_in[10];
    const float* w_hh   = (const float*)d_in[11];
    const float* b_ih   = (const float*)d_in[12];
    const float* b_hh   = (const float*)d_in[13];
    const float* w_out  = (const float*)d_in[14];
    const float* b_out  = (const float*)d_in[15];
    float* out = (float*)d_out;

    k_prep<<<8192, 256>>>(w_ih, w_hh, hpad);
    k_gemms<<<1832, 256>>>(hpad, w_enc, b_enc, w_ih, b_ih, b_hh, ys, embed);

    for (int step = 0; step < OLEN; step++) {
        k_small<<<BB * CC + 512, 256>>>(w_dec, w_conv, step);
        k_e<<<dim3(25, BB), 128>>>(w_att, w_gvec);
        k_ctx<<<dim3(4, BB), 256>>>();
        k_lstm<<<128, 256>>>(step);
    }
    k_out<<<dim3(40, 26), 256>>>(w_out, b_out, out);
}

// round 6
// speedup vs baseline: 2.3935x; 1.0888x over previous
#include <cuda_runtime.h>
#include <cuda_fp16.h>

#define BB 32
#define TT 1000
#define EE 512
#define DD 1024
#define AA 512
#define CC 10
#define FF 100
#define KW 201
#define ODIM_ 5000
#define LL 100
#define OLEN 101
#define SOS_ 4998
#define NROW 4096
#define KCAT2 1536
#define MOUT 3232
#define MOUT_PAD 3328

__device__ __half g_preh[BB * TT * AA];          // fp16 pre, 32.8 MB (L2-hot)
__device__ __half g_hpadh[BB * TT * EE];         // fp16 hpad, 32.8 MB (L2-hot)
__device__ float g_wcat2[NROW * KCAT2];          // 25.2 MB (L2-hot)
__device__ float g_gey[MOUT_PAD * NROW];         // 54.5 MB (streamed, evict-first)
__device__ float g_aw[BB * TT];
__device__ float g_e[BB * TT];
__device__ float g_conv[BB * CC * TT];
__device__ float g_decp[4][BB * AA];
__device__ float g_ctx[BB * EE];
__device__ float g_z[2][BB * DD];
__device__ float g_c[BB * DD];
__device__ float g_zall[MOUT_PAD * DD];

__device__ __forceinline__ float tanh_fast(float x) {
    float y;
    asm("tanh.approx.f32 %0, %1;" : "=f"(y) : "f"(x));
    return y;
}

// ---------- pre-loop kernel 1: init + weight pack + hpad->fp16 ----------
__global__ void k_prep(const float* __restrict__ w_ih, const float* __restrict__ w_hh,
                       const float* __restrict__ hpad) {
    const size_t TOT = 22740224;
    for (size_t i = (size_t)blockIdx.x * 256 + threadIdx.x; i < TOT; i += 2097152) {
        if (i < 32768) {
            g_z[0][i] = 0.f; g_c[i] = 0.f;
        } else if (i < 64768) {
            g_aw[i - 32768] = 1.0f / TT;
        } else if (i < 6356224) {
            int j = (int)(i - 64768);
            int r = j / KCAT2, k = j - r * KCAT2;
            int n = (r & 3) * DD + (r >> 2);
            g_wcat2[j] = (k < EE) ? w_ih[(size_t)n * (DD + EE) + DD + k]
                                  : w_hh[(size_t)n * DD + (k - EE)];
        } else {
            size_t j = i - 6356224;
            g_hpadh[j] = __float2half(hpad[j]);
        }
    }
}

// ---------- pre-loop kernel 2: fused one-time GEMMs ----------
__global__ __launch_bounds__(256) void k_gemms(const float* __restrict__ hpad,
                                               const float* __restrict__ w_enc,
                                               const float* __restrict__ b_enc,
                                               const float* __restrict__ w_ih,
                                               const float* __restrict__ b_ih,
                                               const float* __restrict__ b_hh,
                                               const int* __restrict__ ys,
                                               const float* __restrict__ embed) {
    __shared__ float As[16][132];
    __shared__ float Bs[16][132];
    __shared__ int tok_s[128];
    int tid = threadIdx.x;
    bool is_pre = blockIdx.x >= 832;
    int m0, n0, K;
    if (is_pre) {
        int idx = blockIdx.x - 832;
        m0 = (idx >> 2) * 128; n0 = (idx & 3) * 128; K = 512;
    } else {
        m0 = ((int)blockIdx.x >> 5) * 128; n0 = ((int)blockIdx.x & 31) * 128; K = 1024;
        if (tid < 128) {
            int m = m0 + tid;
            int s = m >> 5, b = m & 31;
            tok_s[tid] = (s == 0 || s > 100) ? SOS_ : ys[b * LL + s - 1];
        }
        __syncthreads();
    }
    float acc[8][8];
#pragma unroll
    for (int i = 0; i < 8; i++)
#pragma unroll
        for (int j = 0; j < 8; j++) acc[i][j] = 0.f;
    int tm0 = (tid >> 4) << 3, tn0 = (tid & 15) << 3;
    for (int k0 = 0; k0 < K; k0 += 16) {
#pragma unroll
        for (int i = 0; i < 2; i++) {
            int lin = tid + (i << 8);
            int row = lin >> 2, kq = (lin & 3) << 2;
            float4 va, vb;
            if (is_pre) {
                va = *(const float4*)(hpad + (size_t)(m0 + row) * 512 + k0 + kq);
                vb = *(const float4*)(w_enc + (size_t)(n0 + row) * 512 + k0 + kq);
            } else {
                va = *(const float4*)(embed + (size_t)tok_s[row] * DD + k0 + kq);
                int r = n0 + row;
                int orig = (r & 3) * DD + (r >> 2);
                vb = *(const float4*)(w_ih + (size_t)orig * (DD + EE) + k0 + kq);
            }
            As[kq + 0][row] = va.x; As[kq + 1][row] = va.y;
            As[kq + 2][row] = va.z; As[kq + 3][row] = va.w;
            Bs[kq + 0][row] = vb.x; Bs[kq + 1][row] = vb.y;
            Bs[kq + 2][row] = vb.z; Bs[kq + 3][row] = vb.w;
        }
        __syncthreads();
#pragma unroll
        for (int kk = 0; kk < 16; kk++) {
            float a[8], b[8];
            *(float4*)&a[0] = *(const float4*)&As[kk][tm0];
            *(float4*)&a[4] = *(const float4*)&As[kk][tm0 + 4];
            *(float4*)&b[0] = *(const float4*)&Bs[kk][tn0];
            *(float4*)&b[4] = *(const float4*)&Bs[kk][tn0 + 4];
#pragma unroll
            for (int i = 0; i < 8; i++)
#pragma unroll
                for (int j = 0; j < 8; j++)
                    acc[i][j] = fmaf(a[i], b[j], acc[i][j]);
        }
        __syncthreads();
    }
#pragma unroll
    for (int i = 0; i < 8; i++) {
        int m_ = m0 + tm0 + i;
#pragma unroll
        for (int j = 0; j < 8; j++) {
            int n_ = n0 + tn0 + j;
            if (is_pre) {
                g_preh[(size_t)m_ * 512 + n_] = __float2half(acc[i][j] + b_enc[n_]);
            } else {
                int orig = (n_ & 3) * DD + (n_ >> 2);
                __stcs(&g_gey[(size_t)m_ * NROW + n_], acc[i][j] + b_ih[orig] + b_hh[orig]);
            }
        }
    }
}

// ---------- per-step: conv(aw) [0..319] + dec GEMM K-split [320..383] ----------
__global__ __launch_bounds__(256) void k_small(const float* __restrict__ w_dec,
                                               const float* __restrict__ w_conv, int step) {
    int blk = blockIdx.x, tid = threadIdx.x;
    if (blk < BB * CC) {
        __shared__ float sm[1408];
        int b = blk / CC, c = blk - b * CC;
        float* aw_s = sm;
        float* wk = sm + 1200;
        for (int i = tid; i < TT + 2 * FF; i += 256)
            aw_s[i] = (i >= FF && i < FF + TT) ? g_aw[b * TT + i - FF] : 0.f;
        for (int i = tid; i < KW; i += 256) wk[i] = w_conv[c * KW + i];
        __syncthreads();
        for (int t = tid; t < TT; t += 256) {
            float s = 0.f;
#pragma unroll 4
            for (int k = 0; k < KW; k++) s = fmaf(wk[k], aw_s[t + k], s);
            g_conv[(b * CC + c) * TT + t] = s;
        }
    } else {
        __shared__ float ws2[32][68];
        __shared__ float zs[64][36];
        int blk2 = blk - BB * CC;
        int ks = blk2 & 3, at = blk2 >> 2;
        int a0 = at * 32;
        int kbase = ks * 256;
        int zr = step & 1;
        int al = tid >> 3, bq = (tid & 7) << 2;
        int bbz = tid >> 3, kk0 = tid & 7;
        const float* zsrc = g_z[zr];
        float a0v = 0.f, a1v = 0.f, a2v = 0.f, a3v = 0.f;
        for (int kc = 0; kc < 4; kc++) {
            int k0 = kbase + kc * 64;
            __syncthreads();
#pragma unroll
            for (int i = 0; i < 2; i++) {
                int lin = tid + (i << 8);
                int row = lin >> 4, kq = (lin & 15) << 2;
                float4 w4 = *(const float4*)(w_dec + (size_t)(a0 + row) * DD + k0 + kq);
                ws2[row][kq + 0] = w4.x; ws2[row][kq + 1] = w4.y;
                ws2[row][kq + 2] = w4.z; ws2[row][kq + 3] = w4.w;
            }
#pragma unroll
            for (int j = 0; j < 8; j++) {
                int kk = kk0 + (j << 3);
                zs[kk][bbz] = zsrc[bbz * DD + k0 + kk];
            }
            __syncthreads();
#pragma unroll
            for (int kk = 0; kk < 64; kk++) {
                float w = ws2[al][kk];
                float4 x = *(const float4*)&zs[kk][bq];
                a0v = fmaf(w, x.x, a0v); a1v = fmaf(w, x.y, a1v);
                a2v = fmaf(w, x.z, a2v); a3v = fmaf(w, x.w, a3v);
            }
        }
        g_decp[ks][(bq + 0) * AA + a0 + al] = a0v;
        g_decp[ks][(bq + 1) * AA + a0 + al] = a1v;
        g_decp[ks][(bq + 2) * AA + a0 + al] = a2v;
        g_decp[ks][(bq + 3) * AA + a0 + al] = a3v;
    }
}

// ---------- per-step: e[b,t], 4-tl ILP ----------
__global__ __launch_bounds__(128) void k_e(const float* __restrict__ w_att,
                                           const float* __restrict__ w_gvec) {
    int b = blockIdx.y, t0 = blockIdx.x * 40;
    int tid = threadIdx.x;
    __shared__ float conv_s[40][10];
    __shared__ float part_s[40][4];
    for (int i = tid; i < 400; i += 128) {
        int c = i / 40, tl = i - c * 40;
        conv_s[tl][c] = g_conv[(b * CC + c) * TT + t0 + tl];
    }
    int a0 = tid * 4;
    float wr[4][10], gg[4], dc[4];
#pragma unroll
    for (int j = 0; j < 4; j++) {
#pragma unroll
        for (int c = 0; c < 10; c++) wr[j][c] = w_att[(a0 + j) * CC + c];
        gg[j] = w_gvec[a0 + j];
        int ai = b * AA + a0 + j;
        dc[j] = g_decp[0][ai] + g_decp[1][ai] + g_decp[2][ai] + g_decp[3][ai];
    }
    __syncthreads();
    int lane = tid & 31, warp = tid >> 5;
    const __half* prep = g_preh + ((size_t)b * TT + t0) * AA + a0;
    for (int tq = 0; tq < 40; tq += 4) {
        uint2 u[4];
#pragma unroll
        for (int q = 0; q < 4; q++)
            u[q] = *(const uint2*)(prep + (size_t)(tq + q) * AA);
        float acc[4];
#pragma unroll
        for (int q = 0; q < 4; q++) {
            __half2 h01 = *reinterpret_cast<__half2*>(&u[q].x);
            __half2 h23 = *reinterpret_cast<__half2*>(&u[q].y);
            float2 f01 = __half22float2(h01);
            float2 f23 = __half22float2(h23);
            float pa[4] = {f01.x, f01.y, f23.x, f23.y};
            float a = 0.f;
#pragma unroll
            for (int j = 0; j < 4; j++) {
                float x = pa[j] + dc[j];
#pragma unroll
                for (int c = 0; c < 10; c++) x = fmaf(conv_s[tq + q][c], wr[j][c], x);
                a = fmaf(gg[j], tanh_fast(x), a);
            }
            acc[q] = a;
        }
#pragma unroll
        for (int s = 16; s; s >>= 1) {
            acc[0] += __shfl_xor_sync(0xffffffffu, acc[0], s);
            acc[1] += __shfl_xor_sync(0xffffffffu, acc[1], s);
            acc[2] += __shfl_xor_sync(0xffffffffu, acc[2], s);
            acc[3] += __shfl_xor_sync(0xffffffffu, acc[3], s);
        }
        if (lane == 0) {
            part_s[tq + 0][warp] = acc[0];
            part_s[tq + 1][warp] = acc[1];
            part_s[tq + 2][warp] = acc[2];
            part_s[tq + 3][warp] = acc[3];
        }
    }
    __syncthreads();
    if (tid < 40)
        g_e[b * TT + t0 + tid] =
            part_s[tid][0] + part_s[tid][1] + part_s[tid][2] + part_s[tid][3];
}

// ---------- per-step: softmax(2e) + ctx (half2, 4-chunk) + aw ----------
__global__ __launch_bounds__(256) void k_ctx() {
    int b = blockIdx.y, ec = blockIdx.x;
    int tid = threadIdx.x;
    __shared__ float wsm[1000];
    __shared__ float red[256];
    __shared__ float2 red2[256];
    const float* ep = g_e + b * TT;
    float m = -1e30f;
    for (int t = tid; t < TT; t += 256) m = fmaxf(m, ep[t]);
    red[tid] = m; __syncthreads();
    for (int s = 128; s; s >>= 1) {
        if (tid < s) red[tid] = fmaxf(red[tid], red[tid + s]);
        __syncthreads();
    }
    float mx = red[0]; __syncthreads();
    float sm = 0.f;
    for (int t = tid; t < TT; t += 256) sm += __expf(2.f * (ep[t] - mx));
    red[tid] = sm; __syncthreads();
    for (int s = 128; s; s >>= 1) {
        if (tid < s) red[tid] += red[tid + s];
        __syncthreads();
    }
    float inv = 1.f / red[0];
    __syncthreads();
    for (int t = tid; t < TT; t += 256) {
        float w = __expf(2.f * (ep[t] - mx)) * inv;
        wsm[t] = w;
        if (ec == 0) g_aw[b * TT + t] = w;
    }
    __syncthreads();
    int el2 = (tid & 63) * 2, h = tid >> 6;   // 4 T-chunks of 250
    int e0 = ec * 128;
    const __half2* hp = (const __half2*)(g_hpadh + ((size_t)b * TT + h * 250) * EE + e0 + el2);
    const float* wp = wsm + h * 250;
    float2 a0 = {0.f, 0.f}, a1 = {0.f, 0.f};
#pragma unroll 1
    for (int i = 0; i < 250; i += 2) {
        __half2 v0 = hp[(size_t)(i + 0) * 256];
        __half2 v1 = hp[(size_t)(i + 1) * 256];
        float2 f0 = __half22float2(v0);
        float2 f1 = __half22float2(v1);
        float w0 = wp[i], w1 = wp[i + 1];
        a0.x = fmaf(w0, f0.x, a0.x); a0.y = fmaf(w0, f0.y, a0.y);
        a1.x = fmaf(w1, f1.x, a1.x); a1.y = fmaf(w1, f1.y, a1.y);
    }
    red2[tid] = make_float2(a0.x + a1.x, a0.y + a1.y);
    __syncthreads();
    if (tid < 64) {
        float2 s = red2[tid];
        float2 s1 = red2[tid + 64];
        float2 s2 = red2[tid + 128];
        float2 s3 = red2[tid + 192];
        g_ctx[b * EE + e0 + tid * 2 + 0] = s.x + s1.x + s2.x + s3.x;
        g_ctx[b * EE + e0 + tid * 2 + 1] = s.y + s1.y + s2.y + s3.y;
    }
}

// ---------- per-step: LSTM gates (K=1536) + cell ----------
__global__ __launch_bounds__(256) void k_lstm(int step) {
    __shared__ float ws[32][68];
    __shared__ float xs[64][36];
    __shared__ float gates_s[32][33];
    int tid = threadIdx.x;
    int r0 = blockIdx.x * 32;
    int zr = step & 1;
    int rl = tid >> 3, b0 = (tid & 7) << 2;
    int bb = tid >> 3, kk0 = tid & 7;
    float acc0 = __ldcs(&g_gey[(size_t)(step * BB + b0 + 0) * NROW + r0 + rl]);
    float acc1 = __ldcs(&g_gey[(size_t)(step * BB + b0 + 1) * NROW + r0 + rl]);
    float acc2 = __ldcs(&g_gey[(size_t)(step * BB + b0 + 2) * NROW + r0 + rl]);
    float acc3 = __ldcs(&g_gey[(size_t)(step * BB + b0 + 3) * NROW + r0 + rl]);
    const float* zsrc = g_z[zr];
    for (int k0 = 0; k0 < KCAT2; k0 += 64) {
#pragma unroll
        for (int i = 0; i < 2; i++) {
            int lin = tid + (i << 8);
            int row = lin >> 4, kq = (lin & 15) << 2;
            float4 w4 = *(const float4*)(g_wcat2 + (size_t)(r0 + row) * KCAT2 + k0 + kq);
            ws[row][kq + 0] = w4.x; ws[row][kq + 1] = w4.y;
            ws[row][kq + 2] = w4.z; ws[row][kq + 3] = w4.w;
        }
#pragma unroll
        for (int j = 0; j < 8; j++) {
            int kk = kk0 + (j << 3);
            int k = k0 + kk;
            float v;
            if (k < EE) v = g_ctx[bb * EE + k];
            else v = zsrc[bb * DD + (k - EE)];
            xs[kk][bb] = v;
        }
        __syncthreads();
#pragma unroll
        for (int kk = 0; kk < 64; kk++) {
            float w = ws[rl][kk];
            float4 x = *(const float4*)&xs[kk][b0];
            acc0 = fmaf(w, x.x, acc0); acc1 = fmaf(w, x.y, acc1);
            acc2 = fmaf(w, x.z, acc2); acc3 = fmaf(w, x.w, acc3);
        }
        __syncthreads();
    }
    gates_s[rl][b0 + 0] = acc0;
    gates_s[rl][b0 + 1] = acc1;
    gates_s[rl][b0 + 2] = acc2;
    gates_s[rl][b0 + 3] = acc3;
    __syncthreads();
    int dl = tid >> 5, b = tid & 31;
    int d = (r0 >> 2) + dl;
    float iv = gates_s[dl * 4 + 0][b];
    float fv = gates_s[dl * 4 + 1][b];
    float gv = gates_s[dl * 4 + 2][b];
    float ov = gates_s[dl * 4 + 3][b];
    float si = 1.f / (1.f + expf(-iv));
    float sf = 1.f / (1.f + expf(-fv));
    float so = 1.f / (1.f + expf(-ov));
    float cn = sf * g_c[b * DD + d] + si * tanhf(gv);
    float zn = so * tanhf(cn);
    g_c[b * DD + d] = cn;
    g_z[zr ^ 1][b * DD + d] = zn;
    __stcs(&g_zall[(size_t)(step * BB + b) * DD + d], zn);
}

// ---------- final: out = z_all @ w_out^T + b_out ----------
__global__ __launch_bounds__(256) void k_out(const float* __restrict__ Bm,
                                             const float* __restrict__ bias,
                                             float* __restrict__ Cout) {
    __shared__ float As[16][132];
    __shared__ float Bs[16][132];
    int tid = threadIdx.x;
    int m0 = blockIdx.y * 128, n0 = blockIdx.x * 128;
    float acc[8][8];
#pragma unroll
    for (int i = 0; i < 8; i++)
#pragma unroll
        for (int j = 0; j < 8; j++) acc[i][j] = 0.f;
    int tm0 = (tid >> 4) << 3, tn0 = (tid & 15) << 3;
    for (int k0 = 0; k0 < DD; k0 += 16) {
#pragma unroll
        for (int i = 0; i < 2; i++) {
            int lin = tid + (i << 8);
            int row = lin >> 2, kq = (lin & 3) << 2;
            float4 va = *(const float4*)(g_zall + (size_t)(m0 + row) * DD + k0 + kq);
            As[kq + 0][row] = va.x; As[kq + 1][row] = va.y;
            As[kq + 2][row] = va.z; As[kq + 3][row] = va.w;
            int nr = n0 + row;
            float4 vb = make_float4(0.f, 0.f, 0.f, 0.f);
            if (nr < ODIM_) vb = *(const float4*)(Bm + (size_t)nr * DD + k0 + kq);
            Bs[kq + 0][row] = vb.x; Bs[kq + 1][row] = vb.y;
            Bs[kq + 2][row] = vb.z; Bs[kq + 3][row] = vb.w;
        }
        __syncthreads();
#pragma unroll
        for (int kk = 0; kk < 16; kk++) {
            float a[8], b[8];
            *(float4*)&a[0] = *(const float4*)&As[kk][tm0];
            *(float4*)&a[4] = *(const float4*)&As[kk][tm0 + 4];
            *(float4*)&b[0] = *(const float4*)&Bs[kk][tn0];
            *(float4*)&b[4] = *(const float4*)&Bs[kk][tn0 + 4];
#pragma unroll
            for (int i = 0; i < 8; i++)
#pragma unroll
                for (int j = 0; j < 8; j++)
                    acc[i][j] = fmaf(a[i], b[j], acc[i][j]);
        }
        __syncthreads();
    }
#pragma unroll
    for (int i = 0; i < 8; i++) {
        int m_ = m0 + tm0 + i;
        if (m_ >= MOUT) continue;
        int b_ = m_ & 31, o_ = m_ >> 5;
#pragma unroll
        for (int j = 0; j < 8; j++) {
            int n_ = n0 + tn0 + j;
            if (n_ >= ODIM_) continue;
            Cout[(size_t)(b_ * OLEN + o_) * ODIM_ + n_] = acc[i][j] + bias[n_];
        }
    }
}

extern "C" void kernel_launch(void* const* d_in, const int* in_sizes, int n_in,
                              void* d_out, int out_size) {
    const float* hpad   = (const float*)d_in[0];
    const int*   ys     = (const int*)d_in[1];
    const float* w_enc  = (const float*)d_in[2];
    const float* b_enc  = (const float*)d_in[3];
    const float* w_dec  = (const float*)d_in[4];
    const float* w_att  = (const float*)d_in[5];
    const float* w_conv = (const float*)d_in[6];
    const float* w_gvec = (const float*)d_in[7];
    const float* embed  = (const float*)d_in[9];
    const float* w_ih   = (const float*)d_in[10];
    const float* w_hh   = (const float*)d_in[11];
    const float* b_ih   = (const float*)d_in[12];
    const float* b_hh   = (const float*)d_in[13];
    const float* w_out  = (const float*)d_in[14];
    const float* b_out  = (const float*)d_in[15];
    float* out = (float*)d_out;

    k_prep<<<8192, 256>>>(w_ih, w_hh, hpad);
    k_gemms<<<1832, 256>>>(hpad, w_enc, b_enc, w_ih, b_ih, b_hh, ys, embed);

    for (int step = 0; step < OLEN; step++) {
        k_small<<<384, 256>>>(w_dec, w_conv, step);
        k_e<<<dim3(25, BB), 128>>>(w_att, w_gvec);
        k_ctx<<<dim3(4, BB), 256>>>();
        k_lstm<<<128, 256>>>(step);
    }
    k_out<<<dim3(40, 26), 256>>>(w_out, b_out, out);
}

// round 7
// speedup vs baseline: 2.9862x; 1.2477x over previous
#include <cuda_runtime.h>
#include <cuda_fp16.h>

#define BB 32
#define TT 1000
#define EE 512
#define DD 1024
#define AA 512
#define CC 10
#define FF 100
#define KW 201
#define ODIM_ 5000
#define LL 100
#define OLEN 101
#define SOS_ 4998
#define NROW 4096
#define KCAT2 1536
#define MOUT 3232
#define MOUT_PAD 3328

__device__ __half g_preh[BB * TT * AA];          // 32.8 MB (L2-hot)
__device__ __half g_hpadh[BB * TT * EE];         // 32.8 MB (L2-hot)
__device__ __half g_wcat2h[NROW * KCAT2];        // 12.6 MB (L2-hot)
__device__ float g_gey[MOUT_PAD * NROW];         // 54.5 MB (streamed)
__device__ float g_aw[BB * TT];
__device__ float g_e[BB * TT];
__device__ float g_conv[BB * CC * TT];
__device__ float g_decp[4][BB * AA];
__device__ float g_ctxp2[2][BB * EE];
__device__ float g_z[2][BB * DD];
__device__ float g_c[BB * DD];
__device__ float g_zall[MOUT_PAD * DD];

__device__ __forceinline__ float tanh_fast(float x) {
    float y;
    asm("tanh.approx.f32 %0, %1;" : "=f"(y) : "f"(x));
    return y;
}

// ---------- pre-loop kernel 1: init + fp16 weight pack + hpad->fp16 ----------
__global__ void k_prep(const float* __restrict__ w_ih, const float* __restrict__ w_hh,
                       const float* __restrict__ hpad) {
    const size_t TOT = 22740224;
    for (size_t i = (size_t)blockIdx.x * 256 + threadIdx.x; i < TOT; i += 2097152) {
        if (i < 32768) {
            g_z[0][i] = 0.f; g_c[i] = 0.f;
        } else if (i < 64768) {
            g_aw[i - 32768] = 1.0f / TT;
        } else if (i < 6356224) {
            int j = (int)(i - 64768);
            int r = j / KCAT2, k = j - r * KCAT2;
            int n = (r & 3) * DD + (r >> 2);
            float v = (k < EE) ? w_ih[(size_t)n * (DD + EE) + DD + k]
                               : w_hh[(size_t)n * DD + (k - EE)];
            g_wcat2h[j] = __float2half(v);
        } else {
            size_t j = i - 6356224;
            g_hpadh[j] = __float2half(hpad[j]);
        }
    }
}

// ---------- pre-loop kernel 2: fused one-time GEMMs ----------
__global__ __launch_bounds__(256) void k_gemms(const float* __restrict__ hpad,
                                               const float* __restrict__ w_enc,
                                               const float* __restrict__ b_enc,
                                               const float* __restrict__ w_ih,
                                               const float* __restrict__ b_ih,
                                               const float* __restrict__ b_hh,
                                               const int* __restrict__ ys,
                                               const float* __restrict__ embed) {
    __shared__ float As[16][132];
    __shared__ float Bs[16][132];
    __shared__ int tok_s[128];
    int tid = threadIdx.x;
    bool is_pre = blockIdx.x >= 832;
    int m0, n0, K;
    if (is_pre) {
        int idx = blockIdx.x - 832;
        m0 = (idx >> 2) * 128; n0 = (idx & 3) * 128; K = 512;
    } else {
        m0 = ((int)blockIdx.x >> 5) * 128; n0 = ((int)blockIdx.x & 31) * 128; K = 1024;
        if (tid < 128) {
            int m = m0 + tid;
            int s = m >> 5, b = m & 31;
            tok_s[tid] = (s == 0 || s > 100) ? SOS_ : ys[b * LL + s - 1];
        }
        __syncthreads();
    }
    float acc[8][8];
#pragma unroll
    for (int i = 0; i < 8; i++)
#pragma unroll
        for (int j = 0; j < 8; j++) acc[i][j] = 0.f;
    int tm0 = (tid >> 4) << 3, tn0 = (tid & 15) << 3;
    for (int k0 = 0; k0 < K; k0 += 16) {
#pragma unroll
        for (int i = 0; i < 2; i++) {
            int lin = tid + (i << 8);
            int row = lin >> 2, kq = (lin & 3) << 2;
            float4 va, vb;
            if (is_pre) {
                va = *(const float4*)(hpad + (size_t)(m0 + row) * 512 + k0 + kq);
                vb = *(const float4*)(w_enc + (size_t)(n0 + row) * 512 + k0 + kq);
            } else {
                va = *(const float4*)(embed + (size_t)tok_s[row] * DD + k0 + kq);
                int r = n0 + row;
                int orig = (r & 3) * DD + (r >> 2);
                vb = *(const float4*)(w_ih + (size_t)orig * (DD + EE) + k0 + kq);
            }
            As[kq + 0][row] = va.x; As[kq + 1][row] = va.y;
            As[kq + 2][row] = va.z; As[kq + 3][row] = va.w;
            Bs[kq + 0][row] = vb.x; Bs[kq + 1][row] = vb.y;
            Bs[kq + 2][row] = vb.z; Bs[kq + 3][row] = vb.w;
        }
        __syncthreads();
#pragma unroll
        for (int kk = 0; kk < 16; kk++) {
            float a[8], b[8];
            *(float4*)&a[0] = *(const float4*)&As[kk][tm0];
            *(float4*)&a[4] = *(const float4*)&As[kk][tm0 + 4];
            *(float4*)&b[0] = *(const float4*)&Bs[kk][tn0];
            *(float4*)&b[4] = *(const float4*)&Bs[kk][tn0 + 4];
#pragma unroll
            for (int i = 0; i < 8; i++)
#pragma unroll
                for (int j = 0; j < 8; j++)
                    acc[i][j] = fmaf(a[i], b[j], acc[i][j]);
        }
        __syncthreads();
    }
#pragma unroll
    for (int i = 0; i < 8; i++) {
        int m_ = m0 + tm0 + i;
#pragma unroll
        for (int j = 0; j < 8; j++) {
            int n_ = n0 + tn0 + j;
            if (is_pre) {
                g_preh[(size_t)m_ * 512 + n_] = __float2half(acc[i][j] + b_enc[n_]);
            } else {
                int orig = (n_ & 3) * DD + (n_ >> 2);
                __stcs(&g_gey[(size_t)m_ * NROW + n_], acc[i][j] + b_ih[orig] + b_hh[orig]);
            }
        }
    }
}

// ---------- per-step: conv(aw) [0..319] + dec GEMM K-split [320..383] ----------
__global__ __launch_bounds__(256) void k_small(const float* __restrict__ w_dec,
                                               const float* __restrict__ w_conv, int step) {
    int blk = blockIdx.x, tid = threadIdx.x;
    if (blk < BB * CC) {
        __shared__ float sm[1408];
        int b = blk / CC, c = blk - b * CC;
        float* aw_s = sm;
        float* wk = sm + 1200;
        for (int i = tid; i < TT + 2 * FF; i += 256)
            aw_s[i] = (i >= FF && i < FF + TT) ? g_aw[b * TT + i - FF] : 0.f;
        for (int i = tid; i < KW; i += 256) wk[i] = w_conv[c * KW + i];
        __syncthreads();
        for (int t = tid; t < TT; t += 256) {
            float s = 0.f;
#pragma unroll 4
            for (int k = 0; k < KW; k++) s = fmaf(wk[k], aw_s[t + k], s);
            g_conv[(b * CC + c) * TT + t] = s;
        }
    } else {
        __shared__ float ws2[32][68];
        __shared__ float zs[64][36];
        int blk2 = blk - BB * CC;
        int ks = blk2 & 3, at = blk2 >> 2;
        int a0 = at * 32;
        int kbase = ks * 256;
        int zr = step & 1;
        int al = tid >> 3, bq = (tid & 7) << 2;
        int bbz = tid >> 3, kk0 = tid & 7;
        const float* zsrc = g_z[zr];
        float a0v = 0.f, a1v = 0.f, a2v = 0.f, a3v = 0.f;
        for (int kc = 0; kc < 4; kc++) {
            int k0 = kbase + kc * 64;
            __syncthreads();
#pragma unroll
            for (int i = 0; i < 2; i++) {
                int lin = tid + (i << 8);
                int row = lin >> 4, kq = (lin & 15) << 2;
                float4 w4 = *(const float4*)(w_dec + (size_t)(a0 + row) * DD + k0 + kq);
                ws2[row][kq + 0] = w4.x; ws2[row][kq + 1] = w4.y;
                ws2[row][kq + 2] = w4.z; ws2[row][kq + 3] = w4.w;
            }
#pragma unroll
            for (int j = 0; j < 8; j++) {
                int kk = kk0 + (j << 3);
                zs[kk][bbz] = zsrc[bbz * DD + k0 + kk];
            }
            __syncthreads();
#pragma unroll
            for (int kk = 0; kk < 64; kk++) {
                float w = ws2[al][kk];
                float4 x = *(const float4*)&zs[kk][bq];
                a0v = fmaf(w, x.x, a0v); a1v = fmaf(w, x.y, a1v);
                a2v = fmaf(w, x.z, a2v); a3v = fmaf(w, x.w, a3v);
            }
        }
        g_decp[ks][(bq + 0) * AA + a0 + al] = a0v;
        g_decp[ks][(bq + 1) * AA + a0 + al] = a1v;
        g_decp[ks][(bq + 2) * AA + a0 + al] = a2v;
        g_decp[ks][(bq + 3) * AA + a0 + al] = a3v;
    }
}

// ---------- per-step: e[b,t], t-chunk 20 (1600 blocks), 4-tl ILP ----------
__global__ __launch_bounds__(128) void k_e(const float* __restrict__ w_att,
                                           const float* __restrict__ w_gvec) {
    int b = blockIdx.y, t0 = blockIdx.x * 20;
    int tid = threadIdx.x;
    __shared__ float conv_s[20][10];
    __shared__ float part_s[20][4];
    for (int i = tid; i < 200; i += 128) {
        int c = i / 20, tl = i - c * 20;
        conv_s[tl][c] = g_conv[(b * CC + c) * TT + t0 + tl];
    }
    int a0 = tid * 4;
    float wr[4][10], gg[4], dc[4];
#pragma unroll
    for (int j = 0; j < 4; j++) {
#pragma unroll
        for (int c = 0; c < 10; c++) wr[j][c] = w_att[(a0 + j) * CC + c];
        gg[j] = w_gvec[a0 + j];
        int ai = b * AA + a0 + j;
        dc[j] = g_decp[0][ai] + g_decp[1][ai] + g_decp[2][ai] + g_decp[3][ai];
    }
    __syncthreads();
    int lane = tid & 31, warp = tid >> 5;
    const __half* prep = g_preh + ((size_t)b * TT + t0) * AA + a0;
    for (int tq = 0; tq < 20; tq += 4) {
        uint2 u[4];
#pragma unroll
        for (int q = 0; q < 4; q++)
            u[q] = *(const uint2*)(prep + (size_t)(tq + q) * AA);
        float acc[4];
#pragma unroll
        for (int q = 0; q < 4; q++) {
            __half2 h01 = *reinterpret_cast<__half2*>(&u[q].x);
            __half2 h23 = *reinterpret_cast<__half2*>(&u[q].y);
            float2 f01 = __half22float2(h01);
            float2 f23 = __half22float2(h23);
            float pa[4] = {f01.x, f01.y, f23.x, f23.y};
            float a = 0.f;
#pragma unroll
            for (int j = 0; j < 4; j++) {
                float x = pa[j] + dc[j];
#pragma unroll
                for (int c = 0; c < 10; c++) x = fmaf(conv_s[tq + q][c], wr[j][c], x);
                a = fmaf(gg[j], tanh_fast(x), a);
            }
            acc[q] = a;
        }
#pragma unroll
        for (int s = 16; s; s >>= 1) {
            acc[0] += __shfl_xor_sync(0xffffffffu, acc[0], s);
            acc[1] += __shfl_xor_sync(0xffffffffu, acc[1], s);
            acc[2] += __shfl_xor_sync(0xffffffffu, acc[2], s);
            acc[3] += __shfl_xor_sync(0xffffffffu, acc[3], s);
        }
        if (lane == 0) {
            part_s[tq + 0][warp] = acc[0];
            part_s[tq + 1][warp] = acc[1];
            part_s[tq + 2][warp] = acc[2];
            part_s[tq + 3][warp] = acc[3];
        }
    }
    __syncthreads();
    if (tid < 20)
        g_e[b * TT + t0 + tid] =
            part_s[tid][0] + part_s[tid][1] + part_s[tid][2] + part_s[tid][3];
}

// ---------- per-step: softmax(2e) + ctx partials (T-split 2) + aw ----------
__global__ __launch_bounds__(256) void k_ctx() {
    int b = blockIdx.y;
    int ec = blockIdx.x & 3, tc = blockIdx.x >> 2;
    int tid = threadIdx.x;
    __shared__ float wsm[500];
    __shared__ float red[256];
    __shared__ float2 red2[256];
    const float* ep = g_e + b * TT;
    float m = -1e30f;
    for (int t = tid; t < TT; t += 256) m = fmaxf(m, ep[t]);
    red[tid] = m; __syncthreads();
    for (int s = 128; s; s >>= 1) {
        if (tid < s) red[tid] = fmaxf(red[tid], red[tid + s]);
        __syncthreads();
    }
    float mx = red[0]; __syncthreads();
    float sm = 0.f;
    for (int t = tid; t < TT; t += 256) sm += __expf(2.f * (ep[t] - mx));
    red[tid] = sm; __syncthreads();
    for (int s = 128; s; s >>= 1) {
        if (tid < s) red[tid] += red[tid + s];
        __syncthreads();
    }
    float inv = 1.f / red[0];
    __syncthreads();
    int tbase = tc * 500;
    for (int i = tid; i < 500; i += 256) {
        float w = __expf(2.f * (ep[tbase + i] - mx)) * inv;
        wsm[i] = w;
        if (ec == 0) g_aw[b * TT + tbase + i] = w;
    }
    __syncthreads();
    int el2 = (tid & 63) * 2, h = tid >> 6;   // 4 sub-chunks of 125
    int e0 = ec * 128;
    const __half2* hp =
        (const __half2*)(g_hpadh + ((size_t)b * TT + tbase + h * 125) * EE + e0 + el2);
    const float* wp = wsm + h * 125;
    float ax = 0.f, ay = 0.f;
#pragma unroll 5
    for (int i = 0; i < 125; i++) {
        float2 f = __half22float2(hp[(size_t)i * 256]);
        float w = wp[i];
        ax = fmaf(w, f.x, ax); ay = fmaf(w, f.y, ay);
    }
    red2[tid] = make_float2(ax, ay);
    __syncthreads();
    if (tid < 64) {
        float2 s0 = red2[tid], s1 = red2[tid + 64];
        float2 s2 = red2[tid + 128], s3 = red2[tid + 192];
        g_ctxp2[tc][b * EE + e0 + tid * 2 + 0] = s0.x + s1.x + s2.x + s3.x;
        g_ctxp2[tc][b * EE + e0 + tid * 2 + 1] = s0.y + s1.y + s2.y + s3.y;
    }
}

// ---------- per-step: LSTM gates (fp16 weights, r-tile 16, 256 blocks) + cell ----------
__global__ __launch_bounds__(128) void k_lstm(int step) {
    __shared__ float ws[16][68];
    __shared__ float xs[64][36];
    __shared__ float gates_s[16][33];
    int tid = threadIdx.x;
    int r0 = blockIdx.x * 16;
    int zr = step & 1;
    int rl = tid >> 3, b0 = (tid & 7) << 2;
    int bb = tid >> 2, kk0 = tid & 3;
    float acc0 = __ldcs(&g_gey[(size_t)(step * BB + b0 + 0) * NROW + r0 + rl]);
    float acc1 = __ldcs(&g_gey[(size_t)(step * BB + b0 + 1) * NROW + r0 + rl]);
    float acc2 = __ldcs(&g_gey[(size_t)(step * BB + b0 + 2) * NROW + r0 + rl]);
    float acc3 = __ldcs(&g_gey[(size_t)(step * BB + b0 + 3) * NROW + r0 + rl]);
    const float* zsrc = g_z[zr];
    int wrow = tid >> 3, wkq = (tid & 7) << 3;
    for (int k0 = 0; k0 < KCAT2; k0 += 64) {
        {
            uint4 w8 = *(const uint4*)(g_wcat2h + (size_t)(r0 + wrow) * KCAT2 + k0 + wkq);
            __half2* hp = (__half2*)&w8;
            float2 f0 = __half22float2(hp[0]);
            float2 f1 = __half22float2(hp[1]);
            float2 f2 = __half22float2(hp[2]);
            float2 f3 = __half22float2(hp[3]);
            ws[wrow][wkq + 0] = f0.x; ws[wrow][wkq + 1] = f0.y;
            ws[wrow][wkq + 2] = f1.x; ws[wrow][wkq + 3] = f1.y;
            ws[wrow][wkq + 4] = f2.x; ws[wrow][wkq + 5] = f2.y;
            ws[wrow][wkq + 6] = f3.x; ws[wrow][wkq + 7] = f3.y;
        }
#pragma unroll
        for (int j = 0; j < 16; j++) {
            int kk = kk0 + (j << 2);
            int k = k0 + kk;
            float v;
            if (k < EE) v = g_ctxp2[0][bb * EE + k] + g_ctxp2[1][bb * EE + k];
            else v = zsrc[bb * DD + (k - EE)];
            xs[kk][bb] = v;
        }
        __syncthreads();
#pragma unroll
        for (int kk = 0; kk < 64; kk++) {
            float w = ws[rl][kk];
            float4 x = *(const float4*)&xs[kk][b0];
            acc0 = fmaf(w, x.x, acc0); acc1 = fmaf(w, x.y, acc1);
            acc2 = fmaf(w, x.z, acc2); acc3 = fmaf(w, x.w, acc3);
        }
        __syncthreads();
    }
    gates_s[rl][b0 + 0] = acc0;
    gates_s[rl][b0 + 1] = acc1;
    gates_s[rl][b0 + 2] = acc2;
    gates_s[rl][b0 + 3] = acc3;
    __syncthreads();
    int dl = tid >> 5, b = tid & 31;
    int d = (r0 >> 2) + dl;
    float iv = gates_s[dl * 4 + 0][b];
    float fv = gates_s[dl * 4 + 1][b];
    float gv = gates_s[dl * 4 + 2][b];
    float ov = gates_s[dl * 4 + 3][b];
    float si = 1.f / (1.f + expf(-iv));
    float sf = 1.f / (1.f + expf(-fv));
    float so = 1.f / (1.f + expf(-ov));
    float cn = sf * g_c[b * DD + d] + si * tanhf(gv);
    float zn = so * tanhf(cn);
    g_c[b * DD + d] = cn;
    g_z[zr ^ 1][b * DD + d] = zn;
    __stcs(&g_zall[(size_t)(step * BB + b) * DD + d], zn);
}

// ---------- final: out = z_all @ w_out^T + b_out ----------
__global__ __launch_bounds__(256) void k_out(const float* __restrict__ Bm,
                                             const float* __restrict__ bias,
                                             float* __restrict__ Cout) {
    __shared__ float As[16][132];
    __shared__ float Bs[16][132];
    int tid = threadIdx.x;
    int m0 = blockIdx.y * 128, n0 = blockIdx.x * 128;
    float acc[8][8];
#pragma unroll
    for (int i = 0; i < 8; i++)
#pragma unroll
        for (int j = 0; j < 8; j++) acc[i][j] = 0.f;
    int tm0 = (tid >> 4) << 3, tn0 = (tid & 15) << 3;
    for (int k0 = 0; k0 < DD; k0 += 16) {
#pragma unroll
        for (int i = 0; i < 2; i++) {
            int lin = tid + (i << 8);
            int row = lin >> 2, kq = (lin & 3) << 2;
            float4 va = *(const float4*)(g_zall + (size_t)(m0 + row) * DD + k0 + kq);
            As[kq + 0][row] = va.x; As[kq + 1][row] = va.y;
            As[kq + 2][row] = va.z; As[kq + 3][row] = va.w;
            int nr = n0 + row;
            float4 vb = make_float4(0.f, 0.f, 0.f, 0.f);
            if (nr < ODIM_) vb = *(const float4*)(Bm + (size_t)nr * DD + k0 + kq);
            Bs[kq + 0][row] = vb.x; Bs[kq + 1][row] = vb.y;
            Bs[kq + 2][row] = vb.z; Bs[kq + 3][row] = vb.w;
        }
        __syncthreads();
#pragma unroll
        for (int kk = 0; kk < 16; kk++) {
            float a[8], b[8];
            *(float4*)&a[0] = *(const float4*)&As[kk][tm0];
            *(float4*)&a[4] = *(const float4*)&As[kk][tm0 + 4];
            *(float4*)&b[0] = *(const float4*)&Bs[kk][tn0];
            *(float4*)&b[4] = *(const float4*)&Bs[kk][tn0 + 4];
#pragma unroll
            for (int i = 0; i < 8; i++)
#pragma unroll
                for (int j = 0; j < 8; j++)
                    acc[i][j] = fmaf(a[i], b[j], acc[i][j]);
        }
        __syncthreads();
    }
#pragma unroll
    for (int i = 0; i < 8; i++) {
        int m_ = m0 + tm0 + i;
        if (m_ >= MOUT) continue;
        int b_ = m_ & 31, o_ = m_ >> 5;
#pragma unroll
        for (int j = 0; j < 8; j++) {
            int n_ = n0 + tn0 + j;
            if (n_ >= ODIM_) continue;
            Cout[(size_t)(b_ * OLEN + o_) * ODIM_ + n_] = acc[i][j] + bias[n_];
        }
    }
}

extern "C" void kernel_launch(void* const* d_in, const int* in_sizes, int n_in,
                              void* d_out, int out_size) {
    const float* hpad   = (const float*)d_in[0];
    const int*   ys     = (const int*)d_in[1];
    const float* w_enc  = (const float*)d_in[2];
    const float* b_enc  = (const float*)d_in[3];
    const float* w_dec  = (const float*)d_in[4];
    const float* w_att  = (const float*)d_in[5];
    const float* w_conv = (const float*)d_in[6];
    const float* w_gvec = (const float*)d_in[7];
    const float* embed  = (const float*)d_in[9];
    const float* w_ih   = (const float*)d_in[10];
    const float* w_hh   = (const float*)d_in[11];
    const float* b_ih   = (const float*)d_in[12];
    const float* b_hh   = (const float*)d_in[13];
    const float* w_out  = (const float*)d_in[14];
    const float* b_out  = (const float*)d_in[15];
    float* out = (float*)d_out;

    k_prep<<<8192, 256>>>(w_ih, w_hh, hpad);
    k_gemms<<<1832, 256>>>(hpad, w_enc, b_enc, w_ih, b_ih, b_hh, ys, embed);

    for (int step = 0; step < OLEN; step++) {
        k_small<<<384, 256>>>(w_dec, w_conv, step);
        k_e<<<dim3(50, BB), 128>>>(w_att, w_gvec);
        k_ctx<<<dim3(8, BB), 256>>>();
        k_lstm<<<256, 128>>>(step);
    }
    k_out<<<dim3(40, 26), 256>>>(w_out, b_out, out);
}